// round 2
// baseline (speedup 1.0000x reference)
#include <cuda_runtime.h>
#include <cstdint>

// Problem shapes (fixed)
#define B_  8
#define C_  64
#define N_  2000
#define T_  12
#define E_  64000
#define HID_ 32

// Scratch: folded matrices and per-(b,n) precomputed tables
__device__ float g_M1[C_ * C_];           // M1[cin*64 + cout]
__device__ float g_M2[C_ * C_];
__device__ float g_A[B_ * N_ * C_];       // A[( b*N + n )*64 + cout]  (includes conv_b)
__device__ float g_Bv[B_ * N_ * C_];

// ---------------------------------------------------------------------------
// Kernel 1: fold W3/W4 with conv_w and scales into 64x64 matrices
// M1[cin][cout] = s1 * sum_h W3[cin,h] * conv_w[cout, h]
// M2[cin][cout] = s2 * sum_h W4[cin,h] * conv_w[cout, HID + h]
// ---------------------------------------------------------------------------
__global__ void fold_M_kernel(const float* __restrict__ W3,
                              const float* __restrict__ W4,
                              const float* __restrict__ cw,
                              const float* __restrict__ s1p,
                              const float* __restrict__ s2p) {
    int id = blockIdx.x * blockDim.x + threadIdx.x;   // 0..4095
    if (id >= C_ * C_) return;
    int cin = id >> 6;
    int cout = id & 63;
    float a = 0.f, b = 0.f;
#pragma unroll
    for (int h = 0; h < HID_; h++) {
        float w3 = W3[cin * HID_ + h];
        float w4 = W4[cin * HID_ + h];
        a += w3 * cw[cout * (2 * HID_) + h];
        b += w4 * cw[cout * (2 * HID_) + HID_ + h];
    }
    g_M1[id] = a * s1p[0];
    g_M2[id] = b * s2p[0];
}

// ---------------------------------------------------------------------------
// Kernel 2: time reduction over T + (B,N,64)@(64,64) projections
// Block: (32 n) x (16 c-slice), grid (ceil(N/32), B). 512 threads.
// Phase 1: each thread reduces x[b,c,n,0:12] against t_up/t_dn.
// Phase 2: 64x64 GEMM per n from smem, write g_A (+conv_b) and g_Bv.
// ---------------------------------------------------------------------------
__global__ __launch_bounds__(512) void stage_AB_kernel(const float* __restrict__ x,
                                                       const float* __restrict__ conv_b) {
    __shared__ float sM1[C_ * C_];   // 16 KB
    __shared__ float sM2[C_ * C_];   // 16 KB
    __shared__ float slt[C_ * 32];   // 8 KB   slt[c*32 + nl]
    __shared__ float srt[C_ * 32];   // 8 KB

    const int tx = threadIdx.x;              // 0..31  (n within tile)
    const int ty = threadIdx.y;              // 0..15
    const int tid = ty * 32 + tx;
    const int b = blockIdx.y;
    const int n0 = blockIdx.x * 32;
    const int n = n0 + tx;

    // cooperative load of M1/M2 (coalesced)
    for (int i = tid; i < C_ * C_; i += 512) {
        sM1[i] = g_M1[i];
        sM2[i] = g_M2[i];
    }

    // Phase 1: per-(c,n) time reduction. Each 12-float row is 16B aligned.
    if (n < N_) {
#pragma unroll
        for (int k = 0; k < 4; k++) {
            int c = ty + 16 * k;
            const float4* p = reinterpret_cast<const float4*>(
                x + ((size_t)(b * C_ + c) * N_ + n) * T_);
            float4 v0 = p[0], v1 = p[1], v2 = p[2];
            float xv[12] = {v0.x, v0.y, v0.z, v0.w,
                            v1.x, v1.y, v1.z, v1.w,
                            v2.x, v2.y, v2.z, v2.w};
            float lt = 0.f, s = 0.f;
#pragma unroll
            for (int t = 0; t < T_; t++) {
                lt += xv[t] * ((float)t * (1.0f / 11.0f));
                s  += xv[t];
            }
            slt[c * 32 + tx] = lt;       // bank-conflict-free (consecutive tx)
            srt[c * 32 + tx] = s - lt;   // since t_dn = 1 - t_up
        }
    }
    __syncthreads();

    // Phase 2: A[b,n,cout] = sum_c slt[n][c]*M1[c][cout] + conv_b[cout]
#pragma unroll
    for (int k = 0; k < 4; k++) {
        int lin = tid + 512 * k;         // 0..2047
        int co = lin & 63;
        int nl = lin >> 6;               // 0..31
        int nn = n0 + nl;
        if (nn < N_) {
            float a = 0.f, bb = 0.f;
#pragma unroll
            for (int c = 0; c < C_; c++) {
                float m1 = sM1[c * 64 + co];     // conflict-free
                float m2 = sM2[c * 64 + co];
                float l = slt[c * 32 + nl];      // broadcast
                float r = srt[c * 32 + nl];
                a  += l * m1;
                bb += r * m2;
            }
            size_t o = ((size_t)b * N_ + nn) * 64 + co;
            g_A[o]  = a + conv_b[co];
            g_Bv[o] = bb;
        }
    }
}

// ---------------------------------------------------------------------------
// Kernel 3: out[b,e,c] = A[b, idx[e], c] + Bv[b, idy[e], c]
// float4-vectorized: 16 float4 per (b,e) row.
// ---------------------------------------------------------------------------
__global__ __launch_bounds__(256) void gather_add_kernel(const int* __restrict__ idx,
                                                         const int* __restrict__ idy,
                                                         float4* __restrict__ out) {
    const unsigned total = (unsigned)B_ * E_ * (C_ / 4);   // 8,192,000
    unsigned g = blockIdx.x * blockDim.x + threadIdx.x;
    if (g >= total) return;
    unsigned c4 = g & 15u;
    unsigned be = g >> 4;                 // b*E + e
    unsigned e = be % (unsigned)E_;
    unsigned b = be / (unsigned)E_;
    int n1 = idx[e];
    int n2 = idy[e];
    const float4* A4 = reinterpret_cast<const float4*>(g_A);
    const float4* B4 = reinterpret_cast<const float4*>(g_Bv);
    float4 a = A4[((size_t)b * N_ + n1) * 16 + c4];
    float4 v = B4[((size_t)b * N_ + n2) * 16 + c4];
    out[g] = make_float4(a.x + v.x, a.y + v.y, a.z + v.z, a.w + v.w);
}

// ---------------------------------------------------------------------------
// Launch
// Inputs (metadata order): x, idx, idy, W1_scale, W2_scale, W3, W4, conv_w, conv_b
// ---------------------------------------------------------------------------
extern "C" void kernel_launch(void* const* d_in, const int* in_sizes, int n_in,
                              void* d_out, int out_size) {
    const float* x   = (const float*)d_in[0];
    const int* idx   = (const int*)d_in[1];
    const int* idy   = (const int*)d_in[2];
    const float* s1  = (const float*)d_in[3];
    const float* s2  = (const float*)d_in[4];
    const float* W3  = (const float*)d_in[5];
    const float* W4  = (const float*)d_in[6];
    const float* cw  = (const float*)d_in[7];
    const float* cb  = (const float*)d_in[8];
    float4* out = (float4*)d_out;

    // K1: fold matrices (4096 threads)
    fold_M_kernel<<<16, 256>>>(W3, W4, cw, s1, s2);

    // K2: stage A/Bv tables
    dim3 blk2(32, 16);
    dim3 grd2((N_ + 31) / 32, B_);
    stage_AB_kernel<<<grd2, blk2>>>(x, cb);

    // K3: gather + add, write out
    const unsigned total = (unsigned)B_ * E_ * (C_ / 4);
    gather_add_kernel<<<(total + 255) / 256, 256>>>(idx, idy, out);
}

// round 3
// speedup vs baseline: 1.3379x; 1.3379x over previous
#include <cuda_runtime.h>
#include <cstdint>

// Problem shapes (fixed)
#define B_  8
#define C_  64
#define N_  2000
#define T_  12
#define E_  64000
#define HID_ 32

// Scratch
__device__ float g_M1[C_ * C_];           // M1[cin*64 + cout]
__device__ float g_M2[C_ * C_];
__device__ float g_A[B_ * N_ * C_];       // A[(b*N + n)*64 + cout]  (includes conv_b)
__device__ float g_Bv[B_ * N_ * C_];

// ---------------------------------------------------------------------------
// Kernel 1: fold W3/W4 with conv_w and scales into 64x64 matrices.
// M1[cin][cout] = s1 * sum_h W3[cin,h]*cw[cout,h]
// M2[cin][cout] = s2 * sum_h W4[cin,h]*cw[cout,32+h]
// 16 blocks x 256 threads; block covers 4 cin x 64 cout.
// cw staged transposed (stride 65 -> conflict-free), W3/W4 rows in registers.
// ---------------------------------------------------------------------------
__global__ __launch_bounds__(256) void fold_M_kernel(const float* __restrict__ W3,
                                                     const float* __restrict__ W4,
                                                     const float* __restrict__ cw,
                                                     const float* __restrict__ s1p,
                                                     const float* __restrict__ s2p) {
    __shared__ float cwt[64 * 65];   // cwt[h][cout], padded
    const int tid = threadIdx.x;

    // Stage cw transposed: global read coalesced, smem write stride-65.
    for (int i = tid; i < 64 * 64; i += 256) {
        int cout = i >> 6;
        int h = i & 63;
        cwt[h * 65 + cout] = cw[i];
    }

    const int cout = tid & 63;
    const int cin = blockIdx.x * 4 + (tid >> 6);

    // W3/W4 rows into registers (8 x float4 each)
    float w3r[HID_], w4r[HID_];
    const float4* p3 = reinterpret_cast<const float4*>(W3 + cin * HID_);
    const float4* p4 = reinterpret_cast<const float4*>(W4 + cin * HID_);
#pragma unroll
    for (int q = 0; q < 8; q++) {
        float4 v3 = p3[q], v4 = p4[q];
        w3r[q * 4 + 0] = v3.x; w3r[q * 4 + 1] = v3.y; w3r[q * 4 + 2] = v3.z; w3r[q * 4 + 3] = v3.w;
        w4r[q * 4 + 0] = v4.x; w4r[q * 4 + 1] = v4.y; w4r[q * 4 + 2] = v4.z; w4r[q * 4 + 3] = v4.w;
    }
    __syncthreads();

    float a = 0.f, b = 0.f;
#pragma unroll
    for (int h = 0; h < HID_; h++) {
        a = fmaf(w3r[h], cwt[h * 65 + cout], a);
        b = fmaf(w4r[h], cwt[(h + HID_) * 65 + cout], b);
    }
    g_M1[cin * 64 + cout] = a * s1p[0];
    g_M2[cin * 64 + cout] = b * s2p[0];
}

// ---------------------------------------------------------------------------
// Kernel 2: time reduction + 64x64 projection, 64-n tile per block.
// 256 threads. Phase 2 register-tiled 4n x 4co x {M1,M2} via LDS.128.
// ---------------------------------------------------------------------------
__global__ __launch_bounds__(256) void stage_AB_kernel(const float* __restrict__ x,
                                                       const float* __restrict__ conv_b) {
    __shared__ float4 sM1[64 * 16];    // [c][co/4]   16 KB
    __shared__ float4 sM2[64 * 16];    // 16 KB
    __shared__ float4 slt4[64 * 16];   // [c][n/4]    16 KB
    __shared__ float4 srt4[64 * 16];   // 16 KB
    float* sM1f = reinterpret_cast<float*>(sM1);
    float* sM2f = reinterpret_cast<float*>(sM2);
    float* slt = reinterpret_cast<float*>(slt4);
    float* srt = reinterpret_cast<float*>(srt4);

    const int tid = threadIdx.x;
    const int b = blockIdx.y;
    const int n0 = blockIdx.x * 64;

    // Cooperative load of folded matrices (coalesced)
    for (int i = tid; i < 64 * 64; i += 256) {
        sM1f[i] = g_M1[i];
        sM2f[i] = g_M2[i];
    }

    // Phase 1: time reduction. 64c x 64n pairs, 16 per thread.
#pragma unroll
    for (int k = 0; k < 16; k++) {
        int p = tid + 256 * k;
        int c = p >> 6;
        int nl = p & 63;
        int n = n0 + nl;
        float lt = 0.f, s = 0.f;
        if (n < N_) {
            const float4* px = reinterpret_cast<const float4*>(
                x + ((size_t)(b * C_ + c) * N_ + n) * T_);
            float4 v0 = px[0], v1 = px[1], v2 = px[2];
            float xv[12] = {v0.x, v0.y, v0.z, v0.w,
                            v1.x, v1.y, v1.z, v1.w,
                            v2.x, v2.y, v2.z, v2.w};
#pragma unroll
            for (int t = 0; t < T_; t++) {
                lt = fmaf(xv[t], (float)t * (1.0f / 11.0f), lt);
                s += xv[t];
            }
        }
        slt[c * 64 + nl] = lt;        // conflict-free (consecutive nl)
        srt[c * 64 + nl] = s - lt;    // t_dn = 1 - t_up
    }
    __syncthreads();

    // Phase 2: A[n][co] = sum_c slt[c][n]*M1[c][co] (+cb), Bv likewise.
    // Thread tile: 4 n x 4 co x 2 matrices.
    const int cg = tid & 15;          // co group (co0 = cg*4)
    const int ng = tid >> 4;          // n group  (n_l0 = ng*4)

    float4 a0 = {0,0,0,0}, a1 = {0,0,0,0}, a2 = {0,0,0,0}, a3 = {0,0,0,0};
    float4 b0 = {0,0,0,0}, b1 = {0,0,0,0}, b2 = {0,0,0,0}, b3 = {0,0,0,0};

#pragma unroll 16
    for (int c = 0; c < 64; c++) {
        float4 m1 = sM1[c * 16 + cg];
        float4 m2 = sM2[c * 16 + cg];
        float4 l = slt4[c * 16 + ng];
        float4 r = srt4[c * 16 + ng];

        a0.x = fmaf(l.x, m1.x, a0.x); a0.y = fmaf(l.x, m1.y, a0.y);
        a0.z = fmaf(l.x, m1.z, a0.z); a0.w = fmaf(l.x, m1.w, a0.w);
        a1.x = fmaf(l.y, m1.x, a1.x); a1.y = fmaf(l.y, m1.y, a1.y);
        a1.z = fmaf(l.y, m1.z, a1.z); a1.w = fmaf(l.y, m1.w, a1.w);
        a2.x = fmaf(l.z, m1.x, a2.x); a2.y = fmaf(l.z, m1.y, a2.y);
        a2.z = fmaf(l.z, m1.z, a2.z); a2.w = fmaf(l.z, m1.w, a2.w);
        a3.x = fmaf(l.w, m1.x, a3.x); a3.y = fmaf(l.w, m1.y, a3.y);
        a3.z = fmaf(l.w, m1.z, a3.z); a3.w = fmaf(l.w, m1.w, a3.w);

        b0.x = fmaf(r.x, m2.x, b0.x); b0.y = fmaf(r.x, m2.y, b0.y);
        b0.z = fmaf(r.x, m2.z, b0.z); b0.w = fmaf(r.x, m2.w, b0.w);
        b1.x = fmaf(r.y, m2.x, b1.x); b1.y = fmaf(r.y, m2.y, b1.y);
        b1.z = fmaf(r.y, m2.z, b1.z); b1.w = fmaf(r.y, m2.w, b1.w);
        b2.x = fmaf(r.z, m2.x, b2.x); b2.y = fmaf(r.z, m2.y, b2.y);
        b2.z = fmaf(r.z, m2.z, b2.z); b2.w = fmaf(r.z, m2.w, b2.w);
        b3.x = fmaf(r.w, m2.x, b3.x); b3.y = fmaf(r.w, m2.y, b3.y);
        b3.z = fmaf(r.w, m2.z, b3.z); b3.w = fmaf(r.w, m2.w, b3.w);
    }

    float4 cbv = reinterpret_cast<const float4*>(conv_b)[cg];
    float4* gA4 = reinterpret_cast<float4*>(g_A);
    float4* gB4 = reinterpret_cast<float4*>(g_Bv);

    float4 av[4] = {a0, a1, a2, a3};
    float4 bv[4] = {b0, b1, b2, b3};
#pragma unroll
    for (int i = 0; i < 4; i++) {
        int n = n0 + ng * 4 + i;
        if (n < N_) {
            size_t o = ((size_t)b * N_ + n) * 16 + cg;
            float4 aa = av[i];
            aa.x += cbv.x; aa.y += cbv.y; aa.z += cbv.z; aa.w += cbv.w;
            gA4[o] = aa;
            gB4[o] = bv[i];
        }
    }
}

// ---------------------------------------------------------------------------
// Kernel 3: out[b,e,c] = A[b, idx[e], c] + Bv[b, idy[e], c]
// ---------------------------------------------------------------------------
__global__ __launch_bounds__(256) void gather_add_kernel(const int* __restrict__ idx,
                                                         const int* __restrict__ idy,
                                                         float4* __restrict__ out) {
    const unsigned total = (unsigned)B_ * E_ * (C_ / 4);   // 8,192,000
    unsigned g = blockIdx.x * blockDim.x + threadIdx.x;
    if (g >= total) return;
    unsigned c4 = g & 15u;
    unsigned be = g >> 4;                 // b*E + e
    unsigned e = be % (unsigned)E_;
    unsigned b = be / (unsigned)E_;
    int n1 = idx[e];
    int n2 = idy[e];
    const float4* A4 = reinterpret_cast<const float4*>(g_A);
    const float4* B4 = reinterpret_cast<const float4*>(g_Bv);
    float4 a = A4[((size_t)b * N_ + n1) * 16 + c4];
    float4 v = B4[((size_t)b * N_ + n2) * 16 + c4];
    out[g] = make_float4(a.x + v.x, a.y + v.y, a.z + v.z, a.w + v.w);
}

// ---------------------------------------------------------------------------
// Launch. Inputs: x, idx, idy, W1_scale, W2_scale, W3, W4, conv_w, conv_b
// ---------------------------------------------------------------------------
extern "C" void kernel_launch(void* const* d_in, const int* in_sizes, int n_in,
                              void* d_out, int out_size) {
    const float* x   = (const float*)d_in[0];
    const int* idx   = (const int*)d_in[1];
    const int* idy   = (const int*)d_in[2];
    const float* s1  = (const float*)d_in[3];
    const float* s2  = (const float*)d_in[4];
    const float* W3  = (const float*)d_in[5];
    const float* W4  = (const float*)d_in[6];
    const float* cw  = (const float*)d_in[7];
    const float* cb  = (const float*)d_in[8];
    float4* out = (float4*)d_out;

    fold_M_kernel<<<16, 256>>>(W3, W4, cw, s1, s2);

    dim3 grd2((N_ + 63) / 64, B_);
    stage_AB_kernel<<<grd2, 256>>>(x, cb);

    const unsigned total = (unsigned)B_ * E_ * (C_ / 4);
    gather_add_kernel<<<(total + 255) / 256, 256>>>(idx, idy, out);
}